// round 1
// baseline (speedup 1.0000x reference)
#include <cuda_runtime.h>

#define B_ 256
#define T_ 512
#define D_ 128
#define U_ 128
#define C_ 64
#define M_ (B_*T_)   // 131072 rows

// Scratch (allocation-free rule: static __device__ arrays)
__device__ float g_H[(size_t)M_ * U_];   // tanh(X@W1+b1)
__device__ float g_F[(size_t)M_ * U_];   // recurrence features

typedef unsigned long long ull;

__device__ __forceinline__ ull pk2(float x, float y) {
    ull r; asm("mov.b64 %0, {%1,%2};" : "=l"(r) : "f"(x), "f"(y)); return r;
}
__device__ __forceinline__ void upk2(ull v, float& x, float& y) {
    asm("mov.b64 {%0,%1}, %2;" : "=f"(x), "=f"(y) : "l"(v));
}
// packed fp32 pair FMA: d.lo = a.lo*b.lo+c.lo ; d.hi = a.hi*b.hi+c.hi
__device__ __forceinline__ ull ffma2(ull a, ull b, ull c) {
    ull d; asm("fma.rn.f32x2 %0, %1, %2, %3;" : "=l"(d) : "l"(a), "l"(b), "l"(c)); return d;
}

// ---------------------------------------------------------------------------
// K1: H[m, u] = tanh( sum_k X[m,k] * W1[k,u] + b1[u] )
// Tile: 64 rows x 128 cols per CTA, 256 threads, micro-tile 8 rows x 4 cols.
// W1 staged in smem pair-interleaved over k: Wp[kp][u] = (W1[2kp][u], W1[2kp+1][u])
// X tile staged row-major; x reads are warp-uniform (broadcast).
// ---------------------------------------------------------------------------
__global__ void __launch_bounds__(256, 2)
k1_in_gemm(const float* __restrict__ X, const float* __restrict__ W1,
           const float* __restrict__ b1)
{
    extern __shared__ float smem[];
    float2* Wp = (float2*)smem;            // [64][128] float2  (64 KB)
    float*  Xs = smem + 16384;             // [64][128] float   (32 KB)
    const int tid = threadIdx.x;
    const int m0 = blockIdx.x * 64;

    // stage W1 pair-interleaved
    {
        const int c4 = (tid & 31) * 4;
        const int kp0 = tid >> 5;
        #pragma unroll
        for (int pass = 0; pass < 8; pass++) {
            int kp = kp0 + pass * 8;
            float4 a = *(const float4*)(W1 + (size_t)(2*kp)   * 128 + c4);
            float4 b = *(const float4*)(W1 + (size_t)(2*kp+1) * 128 + c4);
            float2* w = Wp + kp*128 + c4;
            w[0] = make_float2(a.x, b.x);
            w[1] = make_float2(a.y, b.y);
            w[2] = make_float2(a.z, b.z);
            w[3] = make_float2(a.w, b.w);
        }
    }
    // stage X tile (row-major, coalesced, conflict-free)
    {
        const int q  = (tid & 31) * 4;
        const int r0 = tid >> 5;
        #pragma unroll
        for (int pass = 0; pass < 8; pass++) {
            int row = r0 + pass * 8;
            *(float4*)(Xs + row*128 + q) =
                *(const float4*)(X + (size_t)(m0+row)*128 + q);
        }
    }
    __syncthreads();

    const int tc = tid & 31;   // cols 4tc..4tc+3
    const int tr = tid >> 5;   // rows 8tr..8tr+7 (warp-uniform -> x broadcast)
    ull acc[8][4];
    #pragma unroll
    for (int i = 0; i < 8; i++) {
        #pragma unroll
        for (int c = 0; c < 4; c++) acc[i][c] = 0ULL;
    }

    const float*  xbase = Xs + tr * 8 * 128;
    const float2* wbase = Wp + tc * 4;

    #pragma unroll 8
    for (int kp = 0; kp < 64; kp++) {
        ulonglong2 wv0 = *(const ulonglong2*)(wbase + (size_t)kp*128);
        ulonglong2 wv1 = *(const ulonglong2*)(wbase + (size_t)kp*128 + 2);
        #pragma unroll
        for (int i = 0; i < 8; i++) {
            ull xp = *(const ull*)(xbase + i*128 + 2*kp);
            acc[i][0] = ffma2(xp, wv0.x, acc[i][0]);
            acc[i][1] = ffma2(xp, wv0.y, acc[i][1]);
            acc[i][2] = ffma2(xp, wv1.x, acc[i][2]);
            acc[i][3] = ffma2(xp, wv1.y, acc[i][3]);
        }
    }

    float bb[4];
    #pragma unroll
    for (int c = 0; c < 4; c++) bb[c] = __ldg(b1 + tc*4 + c);

    #pragma unroll
    for (int i = 0; i < 8; i++) {
        int row = m0 + tr*8 + i;
        float4 o; float x, y;
        upk2(acc[i][0], x, y); o.x = tanhf(x + y + bb[0]);
        upk2(acc[i][1], x, y); o.y = tanhf(x + y + bb[1]);
        upk2(acc[i][2], x, y); o.z = tanhf(x + y + bb[2]);
        upk2(acc[i][3], x, y); o.w = tanhf(x + y + bb[3]);
        *(float4*)(g_H + (size_t)row*128 + tc*4) = o;
    }
}

// ---------------------------------------------------------------------------
// K2: recurrence. One CTA per batch row b, 128 threads.
// Thread j owns output column j: holds W2[:,j] as 64 f32x2 pairs in REGISTERS.
// State (128 floats) lives in smem, double-buffered -> 1 __syncthreads per step.
// state reads are warp-uniform broadcasts (cheap crossbar).
// y = h[b,t,:] + tanh(state @ W2 + b2); F[b,t,:] = y; state = y.
// ---------------------------------------------------------------------------
__global__ void __launch_bounds__(128)
k2_recurrence(const float* __restrict__ W2, const float* __restrict__ b2)
{
    __shared__ __align__(16) float st[2][128];
    const int j = threadIdx.x;
    const int b = blockIdx.x;

    ull w[64];
    #pragma unroll
    for (int p = 0; p < 64; p++)
        w[p] = pk2(__ldg(W2 + (size_t)(2*p)*128 + j),
                   __ldg(W2 + (size_t)(2*p+1)*128 + j));
    const float b2v = __ldg(b2 + j);

    st[0][j] = 0.0f;
    __syncthreads();

    const float* Hp = g_H + (size_t)b * (T_*128) + j;
    float*       Fp = g_F + (size_t)b * (T_*128) + j;

    float hv = Hp[0];           // prefetched h for step t
    int buf = 0;
    for (int t = 0; t < T_; t++) {
        float hnext = 0.0f;
        if (t + 1 < T_) hnext = Hp[(size_t)(t+1)*128];   // prefetch next step

        const ulonglong2* sp = (const ulonglong2*)st[buf];
        ull a0 = 0ULL, a1 = 0ULL, a2 = 0ULL, a3 = 0ULL;
        #pragma unroll
        for (int q = 0; q < 32; q += 2) {
            ulonglong2 s01 = sp[q];      // state pairs 2q, 2q+1
            ulonglong2 s23 = sp[q+1];    // state pairs 2q+2, 2q+3
            a0 = ffma2(s01.x, w[2*q+0], a0);
            a1 = ffma2(s01.y, w[2*q+1], a1);
            a2 = ffma2(s23.x, w[2*q+2], a2);
            a3 = ffma2(s23.y, w[2*q+3], a3);
        }
        float x0,y0,x1,y1,x2,y2,x3,y3;
        upk2(a0,x0,y0); upk2(a1,x1,y1); upk2(a2,x2,y2); upk2(a3,x3,y3);
        float s = ((x0+y0)+(x1+y1)) + ((x2+y2)+(x3+y3)) + b2v;

        float yv = hv + tanhf(s);
        st[buf^1][j] = yv;               // write other buffer: no read/write race
        Fp[(size_t)t*128] = yv;
        __syncthreads();                 // publish state for step t+1
        hv = hnext;
        buf ^= 1;
    }
}

// ---------------------------------------------------------------------------
// K3: OUT[m, c] = sum_u F[m,u] * Wc[u,c] + bc[c]
// Tile: 128 rows x 64 cols per CTA, 256 threads, micro-tile 8 rows x 4 cols.
// ---------------------------------------------------------------------------
__global__ void __launch_bounds__(256, 2)
k3_head(const float* __restrict__ Wc, const float* __restrict__ bc,
        float* __restrict__ out)
{
    extern __shared__ float smem[];
    float2* Wp = (float2*)smem;        // [64][64] float2  (32 KB)
    float*  Xs = smem + 8192;          // [128][128] float (64 KB)
    const int tid = threadIdx.x;
    const int m0 = blockIdx.x * 128;

    {
        const int c4  = (tid & 15) * 4;
        const int kp0 = tid >> 4;      // 0..15
        #pragma unroll
        for (int pass = 0; pass < 4; pass++) {
            int kp = kp0 + pass * 16;
            float4 a = *(const float4*)(Wc + (size_t)(2*kp)   * 64 + c4);
            float4 b = *(const float4*)(Wc + (size_t)(2*kp+1) * 64 + c4);
            float2* w = Wp + kp*64 + c4;
            w[0] = make_float2(a.x, b.x);
            w[1] = make_float2(a.y, b.y);
            w[2] = make_float2(a.z, b.z);
            w[3] = make_float2(a.w, b.w);
        }
    }
    {
        const int q  = (tid & 31) * 4;
        const int r0 = tid >> 5;
        #pragma unroll
        for (int pass = 0; pass < 16; pass++) {
            int row = r0 + pass * 8;
            *(float4*)(Xs + row*128 + q) =
                *(const float4*)(g_F + (size_t)(m0+row)*128 + q);
        }
    }
    __syncthreads();

    const int tc = tid & 15;   // cols 4tc..4tc+3
    const int tr = tid >> 4;   // rows 8tr..8tr+7
    ull acc[8][4];
    #pragma unroll
    for (int i = 0; i < 8; i++) {
        #pragma unroll
        for (int c = 0; c < 4; c++) acc[i][c] = 0ULL;
    }

    const float*  xbase = Xs + tr * 8 * 128;
    const float2* wbase = Wp + tc * 4;

    #pragma unroll 8
    for (int kp = 0; kp < 64; kp++) {
        ulonglong2 wv0 = *(const ulonglong2*)(wbase + (size_t)kp*64);
        ulonglong2 wv1 = *(const ulonglong2*)(wbase + (size_t)kp*64 + 2);
        #pragma unroll
        for (int i = 0; i < 8; i++) {
            ull xp = *(const ull*)(xbase + i*128 + 2*kp);
            acc[i][0] = ffma2(xp, wv0.x, acc[i][0]);
            acc[i][1] = ffma2(xp, wv0.y, acc[i][1]);
            acc[i][2] = ffma2(xp, wv1.x, acc[i][2]);
            acc[i][3] = ffma2(xp, wv1.y, acc[i][3]);
        }
    }

    float bb[4];
    #pragma unroll
    for (int c = 0; c < 4; c++) bb[c] = __ldg(bc + tc*4 + c);

    #pragma unroll
    for (int i = 0; i < 8; i++) {
        int row = m0 + tr*8 + i;
        float4 o; float x, y;
        upk2(acc[i][0], x, y); o.x = x + y + bb[0];
        upk2(acc[i][1], x, y); o.y = x + y + bb[1];
        upk2(acc[i][2], x, y); o.z = x + y + bb[2];
        upk2(acc[i][3], x, y); o.w = x + y + bb[3];
        *(float4*)(out + (size_t)row*64 + tc*4) = o;
    }
}

extern "C" void kernel_launch(void* const* d_in, const int* in_sizes, int n_in,
                              void* d_out, int out_size) {
    (void)in_sizes; (void)n_in; (void)out_size;
    const float* X  = (const float*)d_in[0];
    const float* W1 = (const float*)d_in[1];
    const float* b1 = (const float*)d_in[2];
    const float* W2 = (const float*)d_in[3];
    const float* b2 = (const float*)d_in[4];
    const float* Wc = (const float*)d_in[5];
    const float* bc = (const float*)d_in[6];
    float* out = (float*)d_out;

    // Host-side attribute set (not a stream op; safe under graph capture).
    cudaFuncSetAttribute(k1_in_gemm, cudaFuncAttributeMaxDynamicSharedMemorySize, 98304);
    cudaFuncSetAttribute(k3_head,    cudaFuncAttributeMaxDynamicSharedMemorySize, 98304);

    k1_in_gemm<<<M_/64, 256, 98304>>>(X, W1, b1);
    k2_recurrence<<<B_, 128>>>(W2, b2);
    k3_head<<<M_/128, 256, 98304>>>(Wc, bc, out);
}

// round 2
// speedup vs baseline: 1.0047x; 1.0047x over previous
#include <cuda_runtime.h>

#define B_ 256
#define T_ 512
#define D_ 128
#define U_ 128
#define C_ 64
#define M_ (B_*T_)   // 131072 rows

__device__ float g_H[(size_t)M_ * U_];   // tanh(X@W1+b1)
__device__ float g_F[(size_t)M_ * U_];   // recurrence features

typedef unsigned long long ull;

__device__ __forceinline__ ull pk2(float x, float y) {
    ull r; asm("mov.b64 %0, {%1,%2};" : "=l"(r) : "f"(x), "f"(y)); return r;
}
__device__ __forceinline__ void upk2(ull v, float& x, float& y) {
    asm("mov.b64 {%0,%1}, %2;" : "=f"(x), "=f"(y) : "l"(v));
}
__device__ __forceinline__ ull ffma2(ull a, ull b, ull c) {
    ull d; asm("fma.rn.f32x2 %0, %1, %2, %3;" : "=l"(d) : "l"(a), "l"(b), "l"(c)); return d;
}
__device__ __forceinline__ float tanh_fast(float x) {
    float y; asm("tanh.approx.f32 %0, %1;" : "=f"(y) : "f"(x)); return y;
}

// ---------------------------------------------------------------------------
// K1: H = tanh(X @ W1 + b1). Tile 64 rows x 128 cols, 256 thr, micro 8x4.
// kp unrolled by 2; x read as LDS.128 (2 k-pairs), w pair-interleaved in smem.
// ---------------------------------------------------------------------------
__global__ void __launch_bounds__(256, 2)
k1_in_gemm(const float* __restrict__ X, const float* __restrict__ W1,
           const float* __restrict__ b1)
{
    extern __shared__ float smem[];
    float2* Wp = (float2*)smem;            // [64][128] float2  (64 KB)
    float*  Xs = smem + 16384;             // [64][128] float   (32 KB)
    const int tid = threadIdx.x;
    const int m0 = blockIdx.x * 64;

    {   // stage W1 pair-interleaved over k
        const int c4 = (tid & 31) * 4;
        const int kp0 = tid >> 5;
        #pragma unroll
        for (int pass = 0; pass < 8; pass++) {
            int kp = kp0 + pass * 8;
            float4 a = *(const float4*)(W1 + (size_t)(2*kp)   * 128 + c4);
            float4 b = *(const float4*)(W1 + (size_t)(2*kp+1) * 128 + c4);
            float2* w = Wp + kp*128 + c4;
            w[0] = make_float2(a.x, b.x);
            w[1] = make_float2(a.y, b.y);
            w[2] = make_float2(a.z, b.z);
            w[3] = make_float2(a.w, b.w);
        }
    }
    {   // stage X tile row-major
        const int q  = (tid & 31) * 4;
        const int r0 = tid >> 5;
        #pragma unroll
        for (int pass = 0; pass < 8; pass++) {
            int row = r0 + pass * 8;
            *(float4*)(Xs + row*128 + q) =
                *(const float4*)(X + (size_t)(m0+row)*128 + q);
        }
    }
    __syncthreads();

    const int tc = tid & 31;   // cols 4tc..4tc+3
    const int tr = tid >> 5;   // rows 8tr..8tr+7 (warp-uniform -> broadcast x)
    ull acc[8][4];
    #pragma unroll
    for (int i = 0; i < 8; i++)
        #pragma unroll
        for (int c = 0; c < 4; c++) acc[i][c] = 0ULL;

    const float*  xbase = Xs + tr * 8 * 128;
    const float2* wbase = Wp + tc * 4;

    #pragma unroll 4
    for (int kp = 0; kp < 64; kp += 2) {
        ulonglong2 wa0 = *(const ulonglong2*)(wbase + (size_t)kp*128);
        ulonglong2 wa1 = *(const ulonglong2*)(wbase + (size_t)kp*128 + 2);
        ulonglong2 wb0 = *(const ulonglong2*)(wbase + (size_t)(kp+1)*128);
        ulonglong2 wb1 = *(const ulonglong2*)(wbase + (size_t)(kp+1)*128 + 2);
        #pragma unroll
        for (int i = 0; i < 8; i++) {
            ulonglong2 xp = *(const ulonglong2*)(xbase + i*128 + 2*kp); // pairs kp, kp+1
            acc[i][0] = ffma2(xp.x, wa0.x, acc[i][0]);
            acc[i][1] = ffma2(xp.x, wa0.y, acc[i][1]);
            acc[i][2] = ffma2(xp.x, wa1.x, acc[i][2]);
            acc[i][3] = ffma2(xp.x, wa1.y, acc[i][3]);
            acc[i][0] = ffma2(xp.y, wb0.x, acc[i][0]);
            acc[i][1] = ffma2(xp.y, wb0.y, acc[i][1]);
            acc[i][2] = ffma2(xp.y, wb1.x, acc[i][2]);
            acc[i][3] = ffma2(xp.y, wb1.y, acc[i][3]);
        }
    }

    float bb[4];
    #pragma unroll
    for (int c = 0; c < 4; c++) bb[c] = __ldg(b1 + tc*4 + c);

    #pragma unroll
    for (int i = 0; i < 8; i++) {
        int row = m0 + tr*8 + i;
        float4 o; float x, y;
        upk2(acc[i][0], x, y); o.x = tanh_fast(x + y + bb[0]);
        upk2(acc[i][1], x, y); o.y = tanh_fast(x + y + bb[1]);
        upk2(acc[i][2], x, y); o.z = tanh_fast(x + y + bb[2]);
        upk2(acc[i][3], x, y); o.w = tanh_fast(x + y + bb[3]);
        *(float4*)(g_H + (size_t)row*128 + tc*4) = o;
    }
}

// ---------------------------------------------------------------------------
// K2: recurrence. 128 CTAs x 256 threads; each CTA owns TWO batch chains
// (one per 128-thread half) -> single wave, 2 warps/SMSP for latency hiding.
// Thread j of its chain owns output column j; W2[:,j] in registers (64 f32x2).
// State in smem, double-buffered; chains sync independently via named bars.
// ---------------------------------------------------------------------------
__global__ void __launch_bounds__(256)
k2_recurrence(const float* __restrict__ W2, const float* __restrict__ b2)
{
    __shared__ __align__(16) float st[2][2][128];   // [chain][buf][u]
    const int tid   = threadIdx.x;
    const int chain = tid >> 7;
    const int j     = tid & 127;
    const int b     = blockIdx.x * 2 + chain;

    ull w[64];
    #pragma unroll
    for (int p = 0; p < 64; p++)
        w[p] = pk2(__ldg(W2 + (size_t)(2*p)*128 + j),
                   __ldg(W2 + (size_t)(2*p+1)*128 + j));
    const float b2v = __ldg(b2 + j);

    st[chain][0][j] = 0.0f;
    __syncthreads();

    const float* Hp = g_H + (size_t)b * (T_*128) + j;
    float*       Fp = g_F + (size_t)b * (T_*128) + j;

    float hv = Hp[0];
    int buf = 0;
    for (int t = 0; t < T_; t++) {
        float hnext = 0.0f;
        if (t + 1 < T_) hnext = Hp[(size_t)(t+1)*128];

        const ulonglong2* sp = (const ulonglong2*)st[chain][buf];
        ull a0 = 0ULL, a1 = 0ULL, a2 = 0ULL, a3 = 0ULL;
        #pragma unroll
        for (int q = 0; q < 32; q += 2) {
            ulonglong2 s01 = sp[q];
            ulonglong2 s23 = sp[q+1];
            a0 = ffma2(s01.x, w[2*q+0], a0);
            a1 = ffma2(s01.y, w[2*q+1], a1);
            a2 = ffma2(s23.x, w[2*q+2], a2);
            a3 = ffma2(s23.y, w[2*q+3], a3);
        }
        float x0,y0,x1,y1,x2,y2,x3,y3;
        upk2(a0,x0,y0); upk2(a1,x1,y1); upk2(a2,x2,y2); upk2(a3,x3,y3);
        float s = ((x0+y0)+(x1+y1)) + ((x2+y2)+(x3+y3)) + b2v;

        float yv = hv + tanh_fast(s);
        st[chain][buf^1][j] = yv;
        Fp[(size_t)t*128] = yv;
        // per-chain named barrier: 128 threads of this chain only
        asm volatile("bar.sync %0, 128;" :: "r"(chain + 1) : "memory");
        hv = hnext;
        buf ^= 1;
    }
}

// ---------------------------------------------------------------------------
// K3: OUT = F @ Wc + bc. Tile 128 rows x 64 cols, 256 thr, micro 8x4.
// ---------------------------------------------------------------------------
__global__ void __launch_bounds__(256, 2)
k3_head(const float* __restrict__ Wc, const float* __restrict__ bc,
        float* __restrict__ out)
{
    extern __shared__ float smem[];
    float2* Wp = (float2*)smem;        // [64][64] float2  (32 KB)
    float*  Xs = smem + 8192;          // [128][128] float (64 KB)
    const int tid = threadIdx.x;
    const int m0 = blockIdx.x * 128;

    {
        const int c4  = (tid & 15) * 4;
        const int kp0 = tid >> 4;      // 0..15
        #pragma unroll
        for (int pass = 0; pass < 4; pass++) {
            int kp = kp0 + pass * 16;
            float4 a = *(const float4*)(Wc + (size_t)(2*kp)   * 64 + c4);
            float4 b = *(const float4*)(Wc + (size_t)(2*kp+1) * 64 + c4);
            float2* w = Wp + kp*64 + c4;
            w[0] = make_float2(a.x, b.x);
            w[1] = make_float2(a.y, b.y);
            w[2] = make_float2(a.z, b.z);
            w[3] = make_float2(a.w, b.w);
        }
    }
    {
        const int q  = (tid & 31) * 4;
        const int r0 = tid >> 5;
        #pragma unroll
        for (int pass = 0; pass < 16; pass++) {
            int row = r0 + pass * 8;
            *(float4*)(Xs + row*128 + q) =
                *(const float4*)(g_F + (size_t)(m0+row)*128 + q);
        }
    }
    __syncthreads();

    const int tc = tid & 15;   // cols 4tc..4tc+3
    const int tr = tid >> 4;   // rows 8tr..8tr+7
    ull acc[8][4];
    #pragma unroll
    for (int i = 0; i < 8; i++)
        #pragma unroll
        for (int c = 0; c < 4; c++) acc[i][c] = 0ULL;

    const float*  xbase = Xs + tr * 8 * 128;
    const float2* wbase = Wp + tc * 4;

    #pragma unroll 4
    for (int kp = 0; kp < 64; kp += 2) {
        ulonglong2 wa0 = *(const ulonglong2*)(wbase + (size_t)kp*64);
        ulonglong2 wa1 = *(const ulonglong2*)(wbase + (size_t)kp*64 + 2);
        ulonglong2 wb0 = *(const ulonglong2*)(wbase + (size_t)(kp+1)*64);
        ulonglong2 wb1 = *(const ulonglong2*)(wbase + (size_t)(kp+1)*64 + 2);
        #pragma unroll
        for (int i = 0; i < 8; i++) {
            ulonglong2 xp = *(const ulonglong2*)(xbase + i*128 + 2*kp);
            acc[i][0] = ffma2(xp.x, wa0.x, acc[i][0]);
            acc[i][1] = ffma2(xp.x, wa0.y, acc[i][1]);
            acc[i][2] = ffma2(xp.x, wa1.x, acc[i][2]);
            acc[i][3] = ffma2(xp.x, wa1.y, acc[i][3]);
            acc[i][0] = ffma2(xp.y, wb0.x, acc[i][0]);
            acc[i][1] = ffma2(xp.y, wb0.y, acc[i][1]);
            acc[i][2] = ffma2(xp.y, wb1.x, acc[i][2]);
            acc[i][3] = ffma2(xp.y, wb1.y, acc[i][3]);
        }
    }

    float bb[4];
    #pragma unroll
    for (int c = 0; c < 4; c++) bb[c] = __ldg(bc + tc*4 + c);

    #pragma unroll
    for (int i = 0; i < 8; i++) {
        int row = m0 + tr*8 + i;
        float4 o; float x, y;
        upk2(acc[i][0], x, y); o.x = x + y + bb[0];
        upk2(acc[i][1], x, y); o.y = x + y + bb[1];
        upk2(acc[i][2], x, y); o.z = x + y + bb[2];
        upk2(acc[i][3], x, y); o.w = x + y + bb[3];
        *(float4*)(out + (size_t)row*64 + tc*4) = o;
    }
}

extern "C" void kernel_launch(void* const* d_in, const int* in_sizes, int n_in,
                              void* d_out, int out_size) {
    (void)in_sizes; (void)n_in; (void)out_size;
    const float* X  = (const float*)d_in[0];
    const float* W1 = (const float*)d_in[1];
    const float* b1 = (const float*)d_in[2];
    const float* W2 = (const float*)d_in[3];
    const float* b2 = (const float*)d_in[4];
    const float* Wc = (const float*)d_in[5];
    const float* bc = (const float*)d_in[6];
    float* out = (float*)d_out;

    cudaFuncSetAttribute(k1_in_gemm, cudaFuncAttributeMaxDynamicSharedMemorySize, 98304);
    cudaFuncSetAttribute(k3_head,    cudaFuncAttributeMaxDynamicSharedMemorySize, 98304);

    k1_in_gemm<<<M_/64, 256, 98304>>>(X, W1, b1);
    k2_recurrence<<<B_/2, 256>>>(W2, b2);
    k3_head<<<M_/128, 256, 98304>>>(Wc, bc, out);
}